// round 15
// baseline (speedup 1.0000x reference)
#include <cuda_runtime.h>

#define NB   8
#define NT   16
#define IH   112
#define IW   112
#define IC   3
#define NF   16
#define HP   56
#define WP   56
#define HO   54
#define WO   54
#define NCLS 6
#define NBLK_LSTM 392          // 7 x 7 x 8, all co-resident

#define ZX_SMEM_BYTES (9 * 16 * 16 * 16 + 18 * 10 * 16 * 8)   // 36864 + 23040

typedef unsigned long long ull;

// ---------------- f32x2 packed helpers ----------------
__device__ __forceinline__ ull fma2(ull a, ull b, ull c) {
    ull d;
    asm("fma.rn.f32x2 %0, %1, %2, %3;" : "=l"(d) : "l"(a), "l"(b), "l"(c));
    return d;
}
__device__ __forceinline__ ull add2(ull a, ull b) {
    ull d;
    asm("add.rn.f32x2 %0, %1, %2;" : "=l"(d) : "l"(a), "l"(b));
    return d;
}
__device__ __forceinline__ ull pack2(float lo, float hi) {
    ull d;
    asm("mov.b64 %0, {%1, %2};" : "=l"(d) : "f"(lo), "f"(hi));
    return d;
}
__device__ __forceinline__ ull dup2(float v) {
    ull d;
    asm("mov.b64 %0, {%1, %1};" : "=l"(d) : "f"(v));
    return d;
}
__device__ __forceinline__ void unpack2(ull v, float& lo, float& hi) {
    asm("mov.b64 {%0, %1}, %2;" : "=f"(lo), "=f"(hi) : "l"(v));
}

// ---------------- device scratch ----------------
__device__ float  g_pooled[(size_t)NB * NT * HP * WP * NF];        // 25.7 MB
__device__ float  g_zx[(size_t)NB * NT * HO * WO * NF * 4];        // 95.6 MB
__device__ float  g_h[2][(size_t)NB * HO * WO * NF];
__device__ float4 g_wz[9 * 16 * 16];    // [tap][cin][fc] -> (i,f,g,o)
__device__ float4 g_wh[9 * 16 * 16];
__device__ float4 g_bias4[16];

// ---------------- grid barrier state ----------------
__device__ unsigned g_bar_count;
__device__ volatile unsigned g_bar_gen;

__global__ void init_kernel() {
    g_bar_count = 0;
    g_bar_gen = 0;
}

__device__ __forceinline__ void grid_barrier() {
    __syncthreads();
    if (threadIdx.x == 0) {
        __threadfence();
        unsigned gen = g_bar_gen;
        if (atomicAdd(&g_bar_count, 1u) == NBLK_LSTM - 1) {
            g_bar_count = 0;
            __threadfence();
            g_bar_gen = gen + 1;
        } else {
            while (g_bar_gen == gen) { }
            __threadfence();
        }
    }
    __syncthreads();
}

// ---------------- weight transpose / prep ----------------
__global__ void prep_kernel(const float* __restrict__ kz,
                            const float* __restrict__ kh,
                            const float* __restrict__ bias) {
    int i = blockIdx.x * blockDim.x + threadIdx.x;
    if (i < 9 * 16 * 16) {
        int fc  = i & 15;
        int cin = (i >> 4) & 15;
        int kk  = i >> 8;
        int row = kk * 16 + cin;
        const float* s = kz + row * 64;
        g_wz[i] = make_float4(s[fc], s[16 + fc], s[32 + fc], s[48 + fc]);
        s = kh + row * 64;
        g_wh[i] = make_float4(s[fc], s[16 + fc], s[32 + fc], s[48 + fc]);
    }
    if (i < 16)
        g_bias4[i] = make_float4(bias[i], bias[16 + i], bias[32 + i], bias[48 + i]);
}

// ---------------- fused conv7x7 + relu + maxpool2x2 --------------------------
// (reverted to R10-measured best: 8 filters/block, 167us, fma 57.6%)
// Grid (7 stripes, 2 fc-halves, 128 frames). 224 thr = 8 rows x 28 col-pairs.
__global__ __launch_bounds__(224) void conv_pool_kernel(
        const float* __restrict__ x,
        const float* __restrict__ w,
        const float* __restrict__ cb) {
    __shared__ __align__(16) float sw[7 * 7 * 3 * 8];    // 4.7 KB
    __shared__ float scb[8];
    __shared__ __align__(16) float sx[22 * 120 * 3];     // 31.7 KB (rows padded)

    int stripe = blockIdx.x;                             // 0..6
    int fh     = blockIdx.y;                             // 0..1
    int n      = blockIdx.z;
    int tid    = threadIdx.x;

    for (int i = tid; i < 7 * 7 * 3 * 8; i += 224) {
        int f = i & 7, rest = i >> 3;
        sw[i] = w[rest * 16 + fh * 8 + f];
    }
    if (tid < 8) scb[tid] = cb[fh * 8 + tid];

    int r0 = stripe * 16 - 3;
    const float* xn = x + (size_t)n * IH * IW * IC;
    for (int i = tid; i < 22 * 120 * 3; i += 224) {
        int c   = i % 3;
        int col = (i / 3) % 120 - 3;
        int row = i / 360 + r0;
        float v = 0.f;
        if (row >= 0 && row < IH && col >= 0 && col < IW)
            v = xn[(row * IW + col) * 3 + c];
        sx[i] = v;
    }
    __syncthreads();

    int pp  = tid % 28;                  // pooled-px pair: {2pp, 2pp+1}
    int ply = tid / 28;                  // 0..7

    float maxv[16];                      // [2 pooled px][8 filters]
#pragma unroll
    for (int f = 0; f < 16; f++) maxv[f] = 0.f;          // relu floor

#pragma unroll 1
    for (int dy = 0; dy < 2; dy++) {
        ull acc[4][4];                   // [conv col][filter pair]
#pragma unroll
        for (int col = 0; col < 4; col++)
#pragma unroll
            for (int q = 0; q < 4; q++)
                acc[col][q] = pack2(scb[2 * q], scb[2 * q + 1]);

#pragma unroll 1
        for (int ky = 0; ky < 7; ky++) {
            const float4* rp = (const float4*)
                (&sx[(2 * ply + dy + ky) * 360 + 12 * pp]);
            float xf[32];
#pragma unroll
            for (int j = 0; j < 8; j++)
                *(float4*)&xf[4 * j] = rp[j];

#pragma unroll
            for (int kx = 0; kx < 7; kx++) {
#pragma unroll
                for (int c = 0; c < 3; c++) {
                    const ulonglong2* wv =
                        (const ulonglong2*)&sw[((ky * 7 + kx) * 3 + c) * 8];
                    ulonglong2 wa = wv[0];
                    ulonglong2 wb = wv[1];
#pragma unroll
                    for (int col = 0; col < 4; col++) {
                        ull iv = dup2(xf[(kx + col) * 3 + c]);
                        acc[col][0] = fma2(iv, wa.x, acc[col][0]);
                        acc[col][1] = fma2(iv, wa.y, acc[col][1]);
                        acc[col][2] = fma2(iv, wb.x, acc[col][2]);
                        acc[col][3] = fma2(iv, wb.y, acc[col][3]);
                    }
                }
            }
        }
#pragma unroll
        for (int col = 0; col < 4; col++) {
            int half = col >> 1;         // pooled px 0 or 1
#pragma unroll
            for (int q = 0; q < 4; q++) {
                float a, b;
                unpack2(acc[col][q], a, b);
                maxv[half * 8 + 2 * q]     = fmaxf(maxv[half * 8 + 2 * q], a);
                maxv[half * 8 + 2 * q + 1] = fmaxf(maxv[half * 8 + 2 * q + 1], b);
            }
        }
    }

#pragma unroll
    for (int hpx = 0; hpx < 2; hpx++) {
        int px = 2 * pp + hpx;
        float* outp = g_pooled +
            (((size_t)n * HP + stripe * 8 + ply) * WP + px) * NF + fh * 8;
#pragma unroll
        for (int q = 0; q < 2; q++)
            ((float4*)outp)[q] = make_float4(maxv[hpx * 8 + q * 4],
                                             maxv[hpx * 8 + q * 4 + 1],
                                             maxv[hpx * 8 + q * 4 + 2],
                                             maxv[hpx * 8 + q * 4 + 3]);
    }
}

// ---------------- batched zx: VALID 3x3 conv over all 128 frames -------------
// Block: 16-row x 8-col tile; 256 thr = 16 fc x 16 rows; 8 px/thread.
// Input tile stored DUPLICATED (v,v) so FFMA2 broadcast operand is a direct
// LDS.64 — no dup2 MOVs in the hot loop. Dynamic smem (59.9 KB > 48 KB static).
__global__ __launch_bounds__(256) void zx_kernel() {
    extern __shared__ __align__(16) float dynsm[];
    float4* swz4 = (float4*)dynsm;                   // 2304 float4 = 36864 B
    float2* sxt2 = (float2*)(dynsm + 9216);          // 2880 float2 = 23040 B

    int frame = blockIdx.z;
    int y0 = blockIdx.y * 16, x0 = blockIdx.x * 8;
    int tid = threadIdx.x;
    int fc  = tid & 15;
    int r   = tid >> 4;                              // 0..15

    for (int i = tid; i < 2304; i += 256) swz4[i] = g_wz[i];

    const float* xt = g_pooled + (size_t)frame * HP * WP * NF;
    for (int i = tid; i < 2880; i += 256) {
        int ci  = i & 15;
        int col = ((i >> 4) % 10) + x0;
        int row = ((i >> 4) / 10) + y0;
        float v = (row < HP && col < WP) ? xt[(row * WP + col) * NF + ci] : 0.f;
        sxt2[i] = make_float2(v, v);
    }
    __syncthreads();

    float4 b4 = g_bias4[fc];
    ull accL[8], accH[8];
#pragma unroll
    for (int p = 0; p < 8; p++) {
        accL[p] = pack2(b4.x, b4.y);
        accH[p] = pack2(b4.z, b4.w);
    }

#pragma unroll 1
    for (int ky = 0; ky < 3; ky++) {
        const ull* xrow = (const ull*)sxt2 + ((r + ky) * 10) * 16;
#pragma unroll 1
        for (int cin = 0; cin < 16; cin++) {
            ull xv[10];
#pragma unroll
            for (int q = 0; q < 10; q++) xv[q] = xrow[q * 16 + cin];
#pragma unroll
            for (int kx = 0; kx < 3; kx++) {
                const ulonglong2 w2 =
                    ((const ulonglong2*)swz4)[((ky * 3 + kx) * 16 + cin) * 16 + fc];
#pragma unroll
                for (int p = 0; p < 8; p++) {
                    accL[p] = fma2(xv[kx + p], w2.x, accL[p]);
                    accH[p] = fma2(xv[kx + p], w2.y, accH[p]);
                }
            }
        }
    }

    int gy = y0 + r;
    if (gy < HO) {
        ulonglong2* zout = (ulonglong2*)g_zx;
#pragma unroll
        for (int p = 0; p < 8; p++) {
            int gx = x0 + p;
            if (gx < WO) {
                size_t idx = (((size_t)frame * HO + gy) * WO + gx) * 16 + fc;
                zout[idx] = make_ulonglong2(accL[p], accH[p]);
            }
        }
    }
}

// ---------------- persistent ConvLSTM: all 16 steps in one launch ------------
// 392 blocks (7x7x8), 128 thr = 16 fc x 8 rows; 8 px/thread; c in registers.
__global__ __launch_bounds__(128, 3) void lstm_persistent() {
    __shared__ __align__(16) float swh[9 * 16 * 16 * 4];  // 36.8 KB
    __shared__ __align__(16) float2 sht[10 * 10 * 16];    // 12.8 KB (duplicated)

    int bid = blockIdx.x;
    int b   = bid / 49;
    int ty  = (bid / 7) % 7, tx = bid % 7;
    int y0  = ty * 8, x0 = tx * 8;
    int tid = threadIdx.x;
    int fc  = tid & 15;
    int r   = tid >> 4;
    int gy  = y0 + r;

    float4* swh4 = (float4*)swh;
    for (int i = tid; i < 2304; i += 128) swh4[i] = g_wh[i];
    __syncthreads();

    float creg[8];
#pragma unroll
    for (int p = 0; p < 8; p++) creg[p] = 0.f;

    const ulonglong2* zin = (const ulonglong2*)g_zx;

#pragma unroll 1
    for (int t = 0; t < NT; t++) {
        ull accL[8], accH[8];
#pragma unroll
        for (int p = 0; p < 8; p++) { accL[p] = 0ULL; accH[p] = 0ULL; }

        if (t > 0) {
            const float* hb = g_h[t & 1] + (size_t)b * HO * WO * NF;
            for (int i = tid; i < 1600; i += 128) {
                int ci  = i & 15;
                int col = ((i >> 4) % 10) + x0 - 1;
                int row = ((i >> 4) / 10) + y0 - 1;
                float v = (row >= 0 && row < HO && col >= 0 && col < WO)
                              ? hb[(row * WO + col) * NF + ci] : 0.f;
                sht[i] = make_float2(v, v);
            }
            __syncthreads();

#pragma unroll 1
            for (int ky = 0; ky < 3; ky++) {
                const ull* hrow = (const ull*)&sht[((r + ky) * 10) * 16];
#pragma unroll 1
                for (int cin = 0; cin < 16; cin++) {
                    ull xv[10];
#pragma unroll
                    for (int q = 0; q < 10; q++) xv[q] = hrow[q * 16 + cin];
#pragma unroll
                    for (int kx = 0; kx < 3; kx++) {
                        const ulonglong2 w2 =
                            ((const ulonglong2*)swh4)[((ky * 3 + kx) * 16 + cin) * 16 + fc];
#pragma unroll
                        for (int p = 0; p < 8; p++) {
                            accL[p] = fma2(xv[kx + p], w2.x, accL[p]);
                            accH[p] = fma2(xv[kx + p], w2.y, accH[p]);
                        }
                    }
                }
            }
        }

        if (gy < HO) {
            size_t fbase = ((size_t)(b * NT + t) * HO + gy) * WO;
            float* hout = g_h[(t + 1) & 1];
#pragma unroll
            for (int p = 0; p < 8; p++) {
                int gx = x0 + p;
                if (gx >= WO) continue;
                ulonglong2 zx2 = zin[(fbase + gx) * 16 + fc];
                ull zL = add2(zx2.x, accL[p]);
                ull zH = add2(zx2.y, accH[p]);
                float zi, zf, zg, zo;
                unpack2(zL, zi, zf);
                unpack2(zH, zg, zo);

                float ig = __saturatef(0.2f * zi + 0.5f);
                float fg = __saturatef(0.2f * zf + 0.5f);
                float gg = tanhf(zg);
                float og = __saturatef(0.2f * zo + 0.5f);

                float c_new = fg * creg[p] + ig * gg;
                creg[p] = c_new;
                size_t idx = (((size_t)b * HO + gy) * WO + gx) * NF + fc;
                hout[idx] = og * tanhf(c_new);
            }
        }
        grid_barrier();
    }
}

// ---------------- GAP + dense + softmax ----------------
__global__ __launch_bounds__(256) void head_kernel(
        const float* __restrict__ dw,
        const float* __restrict__ db,
        float* __restrict__ out) {
    int b   = blockIdx.x;
    int tid = threadIdx.x;
    const float* hb = g_h[0] + (size_t)b * HO * WO * NF;  // t=15 wrote buffer 0
    int ch = tid & 15, seg = tid >> 4;

    float s = 0.f;
    for (int p = seg; p < HO * WO; p += 16) s += hb[p * NF + ch];

    __shared__ float part[256];
    __shared__ float mean[16];
    part[tid] = s;
    __syncthreads();
    if (tid < 16) {
        float m = 0.f;
        for (int k = 0; k < 16; k++) m += part[k * 16 + tid];
        mean[tid] = m / (float)(HO * WO);
    }
    __syncthreads();
    if (tid == 0) {
        float logits[NCLS];
        for (int j = 0; j < NCLS; j++) {
            float acc = db[j];
            for (int c = 0; c < 16; c++) acc += mean[c] * dw[c * NCLS + j];
            logits[j] = acc;
        }
        float mx = logits[0];
        for (int j = 1; j < NCLS; j++) mx = fmaxf(mx, logits[j]);
        float sum = 0.f;
        for (int j = 0; j < NCLS; j++) { logits[j] = expf(logits[j] - mx); sum += logits[j]; }
        float inv = 1.f / sum;
        for (int j = 0; j < NCLS; j++) out[b * NCLS + j] = logits[j] * inv;
    }
}

// ---------------- launcher ----------------
extern "C" void kernel_launch(void* const* d_in, const int* in_sizes, int n_in,
                              void* d_out, int out_size) {
    const float* x       = (const float*)d_in[0];
    const float* conv_w  = (const float*)d_in[1];
    const float* conv_b  = (const float*)d_in[2];
    const float* lstm_k  = (const float*)d_in[3];
    const float* lstm_rk = (const float*)d_in[4];
    const float* lstm_b  = (const float*)d_in[5];
    const float* dense_w = (const float*)d_in[6];
    const float* dense_b = (const float*)d_in[7];
    float* out = (float*)d_out;

    // host-side attribute set (idempotent, capture-safe, no allocation)
    cudaFuncSetAttribute(zx_kernel,
                         cudaFuncAttributeMaxDynamicSharedMemorySize,
                         ZX_SMEM_BYTES);

    init_kernel<<<1, 1>>>();
    prep_kernel<<<9, 256>>>(lstm_k, lstm_rk, lstm_b);
    conv_pool_kernel<<<dim3(7, 2, NB * NT), 224>>>(x, conv_w, conv_b);
    zx_kernel<<<dim3(7, 4, NB * NT), 256, ZX_SMEM_BYTES>>>();
    lstm_persistent<<<NBLK_LSTM, 128>>>();
    head_kernel<<<NB, 256>>>(dense_w, dense_b, out);
}

// round 16
// speedup vs baseline: 1.0024x; 1.0024x over previous
#include <cuda_runtime.h>

#define NB   8
#define NT   16
#define IH   112
#define IW   112
#define IC   3
#define NF   16
#define HP   56
#define WP   56
#define HO   54
#define WO   54
#define NCLS 6
#define NBLK_LSTM 392          // 7 x 7 x 8, all co-resident

// zx dynamic smem: weights 36864 B + input tile 29*10*16 floats = 18560 B
#define ZX_SMEM_BYTES (36864 + 18560)

typedef unsigned long long ull;

// ---------------- f32x2 packed helpers ----------------
__device__ __forceinline__ ull fma2(ull a, ull b, ull c) {
    ull d;
    asm("fma.rn.f32x2 %0, %1, %2, %3;" : "=l"(d) : "l"(a), "l"(b), "l"(c));
    return d;
}
__device__ __forceinline__ ull add2(ull a, ull b) {
    ull d;
    asm("add.rn.f32x2 %0, %1, %2;" : "=l"(d) : "l"(a), "l"(b));
    return d;
}
__device__ __forceinline__ ull pack2(float lo, float hi) {
    ull d;
    asm("mov.b64 %0, {%1, %2};" : "=l"(d) : "f"(lo), "f"(hi));
    return d;
}
__device__ __forceinline__ ull dup2(float v) {
    ull d;
    asm("mov.b64 %0, {%1, %1};" : "=l"(d) : "f"(v));
    return d;
}
__device__ __forceinline__ void unpack2(ull v, float& lo, float& hi) {
    asm("mov.b64 {%0, %1}, %2;" : "=f"(lo), "=f"(hi) : "l"(v));
}

// ---------------- device scratch ----------------
__device__ float  g_pooled[(size_t)NB * NT * HP * WP * NF];        // 25.7 MB
__device__ float  g_zx[(size_t)NB * NT * HO * WO * NF * 4];        // 95.6 MB
__device__ float  g_h[2][(size_t)NB * HO * WO * NF];
__device__ float4 g_wz[9 * 16 * 16];    // [tap][cin][fc] -> (i,f,g,o)
__device__ float4 g_wh[9 * 16 * 16];
__device__ float4 g_bias4[16];

// ---------------- grid barrier state ----------------
__device__ unsigned g_bar_count;
__device__ volatile unsigned g_bar_gen;

__global__ void init_kernel() {
    g_bar_count = 0;
    g_bar_gen = 0;
}

__device__ __forceinline__ void grid_barrier() {
    __syncthreads();
    if (threadIdx.x == 0) {
        __threadfence();
        unsigned gen = g_bar_gen;
        if (atomicAdd(&g_bar_count, 1u) == NBLK_LSTM - 1) {
            g_bar_count = 0;
            __threadfence();
            g_bar_gen = gen + 1;
        } else {
            while (g_bar_gen == gen) { }
            __threadfence();
        }
    }
    __syncthreads();
}

// ---------------- weight transpose / prep ----------------
__global__ void prep_kernel(const float* __restrict__ kz,
                            const float* __restrict__ kh,
                            const float* __restrict__ bias) {
    int i = blockIdx.x * blockDim.x + threadIdx.x;
    if (i < 9 * 16 * 16) {
        int fc  = i & 15;
        int cin = (i >> 4) & 15;
        int kk  = i >> 8;
        int row = kk * 16 + cin;
        const float* s = kz + row * 64;
        g_wz[i] = make_float4(s[fc], s[16 + fc], s[32 + fc], s[48 + fc]);
        s = kh + row * 64;
        g_wh[i] = make_float4(s[fc], s[16 + fc], s[32 + fc], s[48 + fc]);
    }
    if (i < 16)
        g_bias4[i] = make_float4(bias[i], bias[16 + i], bias[32 + i], bias[48 + i]);
}

// ---------------- fused conv7x7 + relu + maxpool2x2 --------------------------
// (R10-measured best: 8 filters/block, 167us, fma 57.6%)
// Grid (7 stripes, 2 fc-halves, 128 frames). 224 thr = 8 rows x 28 col-pairs.
__global__ __launch_bounds__(224) void conv_pool_kernel(
        const float* __restrict__ x,
        const float* __restrict__ w,
        const float* __restrict__ cb) {
    __shared__ __align__(16) float sw[7 * 7 * 3 * 8];    // 4.7 KB
    __shared__ float scb[8];
    __shared__ __align__(16) float sx[22 * 120 * 3];     // 31.7 KB (rows padded)

    int stripe = blockIdx.x;                             // 0..6
    int fh     = blockIdx.y;                             // 0..1
    int n      = blockIdx.z;
    int tid    = threadIdx.x;

    for (int i = tid; i < 7 * 7 * 3 * 8; i += 224) {
        int f = i & 7, rest = i >> 3;
        sw[i] = w[rest * 16 + fh * 8 + f];
    }
    if (tid < 8) scb[tid] = cb[fh * 8 + tid];

    int r0 = stripe * 16 - 3;
    const float* xn = x + (size_t)n * IH * IW * IC;
    for (int i = tid; i < 22 * 120 * 3; i += 224) {
        int c   = i % 3;
        int col = (i / 3) % 120 - 3;
        int row = i / 360 + r0;
        float v = 0.f;
        if (row >= 0 && row < IH && col >= 0 && col < IW)
            v = xn[(row * IW + col) * 3 + c];
        sx[i] = v;
    }
    __syncthreads();

    int pp  = tid % 28;                  // pooled-px pair: {2pp, 2pp+1}
    int ply = tid / 28;                  // 0..7

    float maxv[16];                      // [2 pooled px][8 filters]
#pragma unroll
    for (int f = 0; f < 16; f++) maxv[f] = 0.f;          // relu floor

#pragma unroll 1
    for (int dy = 0; dy < 2; dy++) {
        ull acc[4][4];                   // [conv col][filter pair]
#pragma unroll
        for (int col = 0; col < 4; col++)
#pragma unroll
            for (int q = 0; q < 4; q++)
                acc[col][q] = pack2(scb[2 * q], scb[2 * q + 1]);

#pragma unroll 1
        for (int ky = 0; ky < 7; ky++) {
            const float4* rp = (const float4*)
                (&sx[(2 * ply + dy + ky) * 360 + 12 * pp]);
            float xf[32];
#pragma unroll
            for (int j = 0; j < 8; j++)
                *(float4*)&xf[4 * j] = rp[j];

#pragma unroll
            for (int kx = 0; kx < 7; kx++) {
#pragma unroll
                for (int c = 0; c < 3; c++) {
                    const ulonglong2* wv =
                        (const ulonglong2*)&sw[((ky * 7 + kx) * 3 + c) * 8];
                    ulonglong2 wa = wv[0];
                    ulonglong2 wb = wv[1];
#pragma unroll
                    for (int col = 0; col < 4; col++) {
                        ull iv = dup2(xf[(kx + col) * 3 + c]);
                        acc[col][0] = fma2(iv, wa.x, acc[col][0]);
                        acc[col][1] = fma2(iv, wa.y, acc[col][1]);
                        acc[col][2] = fma2(iv, wb.x, acc[col][2]);
                        acc[col][3] = fma2(iv, wb.y, acc[col][3]);
                    }
                }
            }
        }
#pragma unroll
        for (int col = 0; col < 4; col++) {
            int half = col >> 1;         // pooled px 0 or 1
#pragma unroll
            for (int q = 0; q < 4; q++) {
                float a, b;
                unpack2(acc[col][q], a, b);
                maxv[half * 8 + 2 * q]     = fmaxf(maxv[half * 8 + 2 * q], a);
                maxv[half * 8 + 2 * q + 1] = fmaxf(maxv[half * 8 + 2 * q + 1], b);
            }
        }
    }

#pragma unroll
    for (int hpx = 0; hpx < 2; hpx++) {
        int px = 2 * pp + hpx;
        float* outp = g_pooled +
            (((size_t)n * HP + stripe * 8 + ply) * WP + px) * NF + fh * 8;
#pragma unroll
        for (int q = 0; q < 2; q++)
            ((float4*)outp)[q] = make_float4(maxv[hpx * 8 + q * 4],
                                             maxv[hpx * 8 + q * 4 + 1],
                                             maxv[hpx * 8 + q * 4 + 2],
                                             maxv[hpx * 8 + q * 4 + 3]);
    }
}

// ---------------- batched zx: VALID 3x3 conv over all 128 frames -------------
// 224 thr = 8 fc-pairs x 28 rows (27 used); each thread: 8 px x 2 fc.
// Per (ky,cin): 10 broadcast LDS.32 + 6 one-wavefront LDS.128 feed 96 FFMA2.
__global__ __launch_bounds__(224) void zx_kernel() {
    extern __shared__ __align__(16) float dynsm[];
    float* swz = dynsm;                  // 9216 floats = 36864 B
    float* sxt = dynsm + 9216;           // 29*10*16 = 4640 floats

    int frame = blockIdx.z;
    int y0 = blockIdx.y * 27;            // {0, 27} — 54 rows exact
    int x0 = blockIdx.x * 8;
    int tid = threadIdx.x;
    int f   = tid & 7;                   // fc-pair index
    int r   = tid >> 3;                  // 0..27 (27 unused)

    float4* swz4 = (float4*)swz;
    for (int i = tid; i < 2304; i += 224) swz4[i] = g_wz[i];

    const float* xt = g_pooled + (size_t)frame * HP * WP * NF;
    for (int i = tid; i < 4640; i += 224) {
        int ci  = i & 15;
        int col = ((i >> 4) % 10) + x0;
        int row = ((i >> 4) / 10) + y0;
        sxt[i] = (row < HP && col < WP) ? xt[(row * WP + col) * NF + ci] : 0.f;
    }
    __syncthreads();

    if (r >= 27) return;                 // no further block syncs below

    int fc0 = 2 * f, fc1 = 2 * f + 1;
    float4 b0 = g_bias4[fc0], b1 = g_bias4[fc1];
    ull aL0[8], aH0[8], aL1[8], aH1[8];
#pragma unroll
    for (int p = 0; p < 8; p++) {
        aL0[p] = pack2(b0.x, b0.y);
        aH0[p] = pack2(b0.z, b0.w);
        aL1[p] = pack2(b1.x, b1.y);
        aH1[p] = pack2(b1.z, b1.w);
    }

    const ulonglong2* wul = (const ulonglong2*)swz;
#pragma unroll 1
    for (int ky = 0; ky < 3; ky++) {
        const float* xrow = &sxt[((r + ky) * 10) * 16];
#pragma unroll 1
        for (int cin = 0; cin < 16; cin++) {
            ull xv[10];
#pragma unroll
            for (int q = 0; q < 10; q++) xv[q] = dup2(xrow[q * 16 + cin]);
#pragma unroll
            for (int kx = 0; kx < 3; kx++) {
                int base = ((ky * 3 + kx) * 16 + cin) * 16;
                ulonglong2 w0 = wul[base + fc0];
                ulonglong2 w1 = wul[base + fc1];
#pragma unroll
                for (int p = 0; p < 8; p++) {
                    aL0[p] = fma2(xv[kx + p], w0.x, aL0[p]);
                    aH0[p] = fma2(xv[kx + p], w0.y, aH0[p]);
                    aL1[p] = fma2(xv[kx + p], w1.x, aL1[p]);
                    aH1[p] = fma2(xv[kx + p], w1.y, aH1[p]);
                }
            }
        }
    }

    int gy = y0 + r;                     // always < 54
    ulonglong2* zout = (ulonglong2*)g_zx;
#pragma unroll
    for (int p = 0; p < 8; p++) {
        int gx = x0 + p;
        if (gx < WO) {
            size_t base = (((size_t)frame * HO + gy) * WO + gx) * 16;
            zout[base + fc0] = make_ulonglong2(aL0[p], aH0[p]);
            zout[base + fc1] = make_ulonglong2(aL1[p], aH1[p]);
        }
    }
}

// ---------------- persistent ConvLSTM: all 16 steps in one launch ------------
// 392 blocks (7x7x8), 128 thr = 16 fc x 8 rows; 8 px/thread; c in registers.
__global__ __launch_bounds__(128, 3) void lstm_persistent() {
    __shared__ __align__(16) float swh[9 * 16 * 16 * 4];  // 36.8 KB
    __shared__ __align__(16) float2 sht[10 * 10 * 16];    // 12.8 KB (duplicated)

    int bid = blockIdx.x;
    int b   = bid / 49;
    int ty  = (bid / 7) % 7, tx = bid % 7;
    int y0  = ty * 8, x0 = tx * 8;
    int tid = threadIdx.x;
    int fc  = tid & 15;
    int r   = tid >> 4;
    int gy  = y0 + r;

    float4* swh4 = (float4*)swh;
    for (int i = tid; i < 2304; i += 128) swh4[i] = g_wh[i];
    __syncthreads();

    float creg[8];
#pragma unroll
    for (int p = 0; p < 8; p++) creg[p] = 0.f;

    const ulonglong2* zin = (const ulonglong2*)g_zx;

#pragma unroll 1
    for (int t = 0; t < NT; t++) {
        ull accL[8], accH[8];
#pragma unroll
        for (int p = 0; p < 8; p++) { accL[p] = 0ULL; accH[p] = 0ULL; }

        if (t > 0) {
            const float* hb = g_h[t & 1] + (size_t)b * HO * WO * NF;
            for (int i = tid; i < 1600; i += 128) {
                int ci  = i & 15;
                int col = ((i >> 4) % 10) + x0 - 1;
                int row = ((i >> 4) / 10) + y0 - 1;
                float v = (row >= 0 && row < HO && col >= 0 && col < WO)
                              ? hb[(row * WO + col) * NF + ci] : 0.f;
                sht[i] = make_float2(v, v);
            }
            __syncthreads();

#pragma unroll 1
            for (int ky = 0; ky < 3; ky++) {
                const ull* hrow = (const ull*)&sht[((r + ky) * 10) * 16];
#pragma unroll 1
                for (int cin = 0; cin < 16; cin++) {
                    ull xv[10];
#pragma unroll
                    for (int q = 0; q < 10; q++) xv[q] = hrow[q * 16 + cin];
#pragma unroll
                    for (int kx = 0; kx < 3; kx++) {
                        const ulonglong2 w2 =
                            ((const ulonglong2*)swh4)[((ky * 3 + kx) * 16 + cin) * 16 + fc];
#pragma unroll
                        for (int p = 0; p < 8; p++) {
                            accL[p] = fma2(xv[kx + p], w2.x, accL[p]);
                            accH[p] = fma2(xv[kx + p], w2.y, accH[p]);
                        }
                    }
                }
            }
        }

        if (gy < HO) {
            size_t fbase = ((size_t)(b * NT + t) * HO + gy) * WO;
            float* hout = g_h[(t + 1) & 1];
#pragma unroll
            for (int p = 0; p < 8; p++) {
                int gx = x0 + p;
                if (gx >= WO) continue;
                ulonglong2 zx2 = zin[(fbase + gx) * 16 + fc];
                ull zL = add2(zx2.x, accL[p]);
                ull zH = add2(zx2.y, accH[p]);
                float zi, zf, zg, zo;
                unpack2(zL, zi, zf);
                unpack2(zH, zg, zo);

                float ig = __saturatef(0.2f * zi + 0.5f);
                float fg = __saturatef(0.2f * zf + 0.5f);
                float gg = tanhf(zg);
                float og = __saturatef(0.2f * zo + 0.5f);

                float c_new = fg * creg[p] + ig * gg;
                creg[p] = c_new;
                size_t idx = (((size_t)b * HO + gy) * WO + gx) * NF + fc;
                hout[idx] = og * tanhf(c_new);
            }
        }
        grid_barrier();
    }
}

// ---------------- GAP + dense + softmax ----------------
__global__ __launch_bounds__(256) void head_kernel(
        const float* __restrict__ dw,
        const float* __restrict__ db,
        float* __restrict__ out) {
    int b   = blockIdx.x;
    int tid = threadIdx.x;
    const float* hb = g_h[0] + (size_t)b * HO * WO * NF;  // t=15 wrote buffer 0
    int ch = tid & 15, seg = tid >> 4;

    float s = 0.f;
    for (int p = seg; p < HO * WO; p += 16) s += hb[p * NF + ch];

    __shared__ float part[256];
    __shared__ float mean[16];
    part[tid] = s;
    __syncthreads();
    if (tid < 16) {
        float m = 0.f;
        for (int k = 0; k < 16; k++) m += part[k * 16 + tid];
        mean[tid] = m / (float)(HO * WO);
    }
    __syncthreads();
    if (tid == 0) {
        float logits[NCLS];
        for (int j = 0; j < NCLS; j++) {
            float acc = db[j];
            for (int c = 0; c < 16; c++) acc += mean[c] * dw[c * NCLS + j];
            logits[j] = acc;
        }
        float mx = logits[0];
        for (int j = 1; j < NCLS; j++) mx = fmaxf(mx, logits[j]);
        float sum = 0.f;
        for (int j = 0; j < NCLS; j++) { logits[j] = expf(logits[j] - mx); sum += logits[j]; }
        float inv = 1.f / sum;
        for (int j = 0; j < NCLS; j++) out[b * NCLS + j] = logits[j] * inv;
    }
}

// ---------------- launcher ----------------
extern "C" void kernel_launch(void* const* d_in, const int* in_sizes, int n_in,
                              void* d_out, int out_size) {
    const float* x       = (const float*)d_in[0];
    const float* conv_w  = (const float*)d_in[1];
    const float* conv_b  = (const float*)d_in[2];
    const float* lstm_k  = (const float*)d_in[3];
    const float* lstm_rk = (const float*)d_in[4];
    const float* lstm_b  = (const float*)d_in[5];
    const float* dense_w = (const float*)d_in[6];
    const float* dense_b = (const float*)d_in[7];
    float* out = (float*)d_out;

    // host-side attribute set (idempotent, capture-safe, no allocation)
    cudaFuncSetAttribute(zx_kernel,
                         cudaFuncAttributeMaxDynamicSharedMemorySize,
                         ZX_SMEM_BYTES);

    init_kernel<<<1, 1>>>();
    prep_kernel<<<9, 256>>>(lstm_k, lstm_rk, lstm_b);
    conv_pool_kernel<<<dim3(7, 2, NB * NT), 224>>>(x, conv_w, conv_b);
    zx_kernel<<<dim3(7, 2, NB * NT), 224, ZX_SMEM_BYTES>>>();
    lstm_persistent<<<NBLK_LSTM, 128>>>();
    head_kernel<<<NB, 256>>>(dense_w, dense_b, out);
}

// round 17
// speedup vs baseline: 1.0384x; 1.0359x over previous
#include <cuda_runtime.h>

#define NB   8
#define NT   16
#define IH   112
#define IW   112
#define IC   3
#define NF   16
#define HP   56
#define WP   56
#define HO   54
#define WO   54
#define NCLS 6
#define NBLK_LSTM 392          // 7 x 7 x 8, all co-resident

#define ZX_XSTRIDE 164         // padded row stride (floats): 656B -> bank shift 4
#define ZX_SMEM_BYTES (36864 + 29 * ZX_XSTRIDE * 4)   // weights + padded tile
#define LH_STRIDE 161          // lstm sht row stride (float2): 1288B -> shift 2

typedef unsigned long long ull;

// ---------------- f32x2 packed helpers ----------------
__device__ __forceinline__ ull fma2(ull a, ull b, ull c) {
    ull d;
    asm("fma.rn.f32x2 %0, %1, %2, %3;" : "=l"(d) : "l"(a), "l"(b), "l"(c));
    return d;
}
__device__ __forceinline__ ull add2(ull a, ull b) {
    ull d;
    asm("add.rn.f32x2 %0, %1, %2;" : "=l"(d) : "l"(a), "l"(b));
    return d;
}
__device__ __forceinline__ ull pack2(float lo, float hi) {
    ull d;
    asm("mov.b64 %0, {%1, %2};" : "=l"(d) : "f"(lo), "f"(hi));
    return d;
}
__device__ __forceinline__ ull dup2(float v) {
    ull d;
    asm("mov.b64 %0, {%1, %1};" : "=l"(d) : "f"(v));
    return d;
}
__device__ __forceinline__ void unpack2(ull v, float& lo, float& hi) {
    asm("mov.b64 {%0, %1}, %2;" : "=f"(lo), "=f"(hi) : "l"(v));
}

// ---------------- device scratch ----------------
__device__ float  g_pooled[(size_t)NB * NT * HP * WP * NF];        // 25.7 MB
__device__ float  g_zx[(size_t)NB * NT * HO * WO * NF * 4];        // 95.6 MB
__device__ float  g_h[2][(size_t)NB * HO * WO * NF];
__device__ ull    g_wzL[9 * 16 * 16];   // [tap][cin][fc] -> (i,f) packed
__device__ ull    g_wzH[9 * 16 * 16];   // [tap][cin][fc] -> (g,o) packed
__device__ float4 g_wh[9 * 16 * 16];    // [tap][cin][fc] -> (i,f,g,o)
__device__ float4 g_bias4[16];

// ---------------- grid barrier state ----------------
__device__ unsigned g_bar_count;
__device__ volatile unsigned g_bar_gen;

__global__ void init_kernel() {
    g_bar_count = 0;
    g_bar_gen = 0;
}

__device__ __forceinline__ void grid_barrier() {
    __syncthreads();
    if (threadIdx.x == 0) {
        __threadfence();
        unsigned gen = g_bar_gen;
        if (atomicAdd(&g_bar_count, 1u) == NBLK_LSTM - 1) {
            g_bar_count = 0;
            __threadfence();
            g_bar_gen = gen + 1;
        } else {
            while (g_bar_gen == gen) { }
            __threadfence();
        }
    }
    __syncthreads();
}

// ---------------- weight transpose / prep ----------------
__global__ void prep_kernel(const float* __restrict__ kz,
                            const float* __restrict__ kh,
                            const float* __restrict__ bias) {
    int i = blockIdx.x * blockDim.x + threadIdx.x;
    if (i < 9 * 16 * 16) {
        int fc  = i & 15;
        int cin = (i >> 4) & 15;
        int kk  = i >> 8;
        int row = kk * 16 + cin;
        const float* s = kz + row * 64;
        g_wzL[i] = pack2(s[fc], s[16 + fc]);
        g_wzH[i] = pack2(s[32 + fc], s[48 + fc]);
        s = kh + row * 64;
        g_wh[i] = make_float4(s[fc], s[16 + fc], s[32 + fc], s[48 + fc]);
    }
    if (i < 16)
        g_bias4[i] = make_float4(bias[i], bias[16 + i], bias[32 + i], bias[48 + i]);
}

// ---------------- fused conv7x7 + relu + maxpool2x2 --------------------------
// (R10-measured best: 8 filters/block, 167us, fma 57.6%)
__global__ __launch_bounds__(224) void conv_pool_kernel(
        const float* __restrict__ x,
        const float* __restrict__ w,
        const float* __restrict__ cb) {
    __shared__ __align__(16) float sw[7 * 7 * 3 * 8];    // 4.7 KB
    __shared__ float scb[8];
    __shared__ __align__(16) float sx[22 * 120 * 3];     // 31.7 KB (rows padded)

    int stripe = blockIdx.x;                             // 0..6
    int fh     = blockIdx.y;                             // 0..1
    int n      = blockIdx.z;
    int tid    = threadIdx.x;

    for (int i = tid; i < 7 * 7 * 3 * 8; i += 224) {
        int f = i & 7, rest = i >> 3;
        sw[i] = w[rest * 16 + fh * 8 + f];
    }
    if (tid < 8) scb[tid] = cb[fh * 8 + tid];

    int r0 = stripe * 16 - 3;
    const float* xn = x + (size_t)n * IH * IW * IC;
    for (int i = tid; i < 22 * 120 * 3; i += 224) {
        int c   = i % 3;
        int col = (i / 3) % 120 - 3;
        int row = i / 360 + r0;
        float v = 0.f;
        if (row >= 0 && row < IH && col >= 0 && col < IW)
            v = xn[(row * IW + col) * 3 + c];
        sx[i] = v;
    }
    __syncthreads();

    int pp  = tid % 28;                  // pooled-px pair: {2pp, 2pp+1}
    int ply = tid / 28;                  // 0..7

    float maxv[16];                      // [2 pooled px][8 filters]
#pragma unroll
    for (int f = 0; f < 16; f++) maxv[f] = 0.f;          // relu floor

#pragma unroll 1
    for (int dy = 0; dy < 2; dy++) {
        ull acc[4][4];                   // [conv col][filter pair]
#pragma unroll
        for (int col = 0; col < 4; col++)
#pragma unroll
            for (int q = 0; q < 4; q++)
                acc[col][q] = pack2(scb[2 * q], scb[2 * q + 1]);

#pragma unroll 1
        for (int ky = 0; ky < 7; ky++) {
            const float4* rp = (const float4*)
                (&sx[(2 * ply + dy + ky) * 360 + 12 * pp]);
            float xf[32];
#pragma unroll
            for (int j = 0; j < 8; j++)
                *(float4*)&xf[4 * j] = rp[j];

#pragma unroll
            for (int kx = 0; kx < 7; kx++) {
#pragma unroll
                for (int c = 0; c < 3; c++) {
                    const ulonglong2* wv =
                        (const ulonglong2*)&sw[((ky * 7 + kx) * 3 + c) * 8];
                    ulonglong2 wa = wv[0];
                    ulonglong2 wb = wv[1];
#pragma unroll
                    for (int col = 0; col < 4; col++) {
                        ull iv = dup2(xf[(kx + col) * 3 + c]);
                        acc[col][0] = fma2(iv, wa.x, acc[col][0]);
                        acc[col][1] = fma2(iv, wa.y, acc[col][1]);
                        acc[col][2] = fma2(iv, wb.x, acc[col][2]);
                        acc[col][3] = fma2(iv, wb.y, acc[col][3]);
                    }
                }
            }
        }
#pragma unroll
        for (int col = 0; col < 4; col++) {
            int half = col >> 1;         // pooled px 0 or 1
#pragma unroll
            for (int q = 0; q < 4; q++) {
                float a, b;
                unpack2(acc[col][q], a, b);
                maxv[half * 8 + 2 * q]     = fmaxf(maxv[half * 8 + 2 * q], a);
                maxv[half * 8 + 2 * q + 1] = fmaxf(maxv[half * 8 + 2 * q + 1], b);
            }
        }
    }

#pragma unroll
    for (int hpx = 0; hpx < 2; hpx++) {
        int px = 2 * pp + hpx;
        float* outp = g_pooled +
            (((size_t)n * HP + stripe * 8 + ply) * WP + px) * NF + fh * 8;
#pragma unroll
        for (int q = 0; q < 2; q++)
            ((float4*)outp)[q] = make_float4(maxv[hpx * 8 + q * 4],
                                             maxv[hpx * 8 + q * 4 + 1],
                                             maxv[hpx * 8 + q * 4 + 2],
                                             maxv[hpx * 8 + q * 4 + 3]);
    }
}

// ---------------- batched zx: VALID 3x3 conv over all 128 frames -------------
// 224 thr = 8 fc-pairs x 28 rows (27 used); each thread: 8 px x 2 fc.
// Tile rows padded (bank shift 4/row); weights split L/H so each fc-pair
// LDS.128 covers contiguous 128B (1 wavefront).
__global__ __launch_bounds__(224) void zx_kernel() {
    extern __shared__ __align__(16) float dynsm[];
    ull*   swL = (ull*)dynsm;            // 2304 ull = 18432 B
    ull*   swH = swL + 2304;             // 2304 ull = 18432 B
    float* sxt = dynsm + 9216;           // 29 * ZX_XSTRIDE floats

    int frame = blockIdx.z;
    int y0 = blockIdx.y * 27;            // {0, 27}
    int x0 = blockIdx.x * 8;
    int tid = threadIdx.x;
    int f   = tid & 7;                   // fc-pair index
    int r   = tid >> 3;                  // 0..27 (27 unused)

    for (int i = tid; i < 2304; i += 224) {
        swL[i] = g_wzL[i];
        swH[i] = g_wzH[i];
    }

    const float* xt = g_pooled + (size_t)frame * HP * WP * NF;
    for (int i = tid; i < 4640; i += 224) {
        int ci  = i & 15;
        int cw  = (i >> 4) % 10;
        int row = (i >> 4) / 10;
        int col = cw + x0;
        int grow = row + y0;
        sxt[row * ZX_XSTRIDE + cw * 16 + ci] =
            (grow < HP && col < WP) ? xt[(grow * WP + col) * NF + ci] : 0.f;
    }
    __syncthreads();

    if (r >= 27) return;

    int fc0 = 2 * f, fc1 = 2 * f + 1;
    float4 b0 = g_bias4[fc0], b1 = g_bias4[fc1];
    ull aL0[8], aH0[8], aL1[8], aH1[8];
#pragma unroll
    for (int p = 0; p < 8; p++) {
        aL0[p] = pack2(b0.x, b0.y);
        aH0[p] = pack2(b0.z, b0.w);
        aL1[p] = pack2(b1.x, b1.y);
        aH1[p] = pack2(b1.z, b1.w);
    }

#pragma unroll 1
    for (int ky = 0; ky < 3; ky++) {
        const float* xrow = &sxt[(r + ky) * ZX_XSTRIDE];
#pragma unroll 1
        for (int cin = 0; cin < 16; cin++) {
            ull xv[10];
#pragma unroll
            for (int q = 0; q < 10; q++) xv[q] = dup2(xrow[q * 16 + cin]);
#pragma unroll
            for (int kx = 0; kx < 3; kx++) {
                int base = ((ky * 3 + kx) * 16 + cin) * 16 + fc0;
                ulonglong2 wl = *(const ulonglong2*)&swL[base];  // (fc0.L, fc1.L)
                ulonglong2 wh = *(const ulonglong2*)&swH[base];  // (fc0.H, fc1.H)
#pragma unroll
                for (int p = 0; p < 8; p++) {
                    aL0[p] = fma2(xv[kx + p], wl.x, aL0[p]);
                    aL1[p] = fma2(xv[kx + p], wl.y, aL1[p]);
                    aH0[p] = fma2(xv[kx + p], wh.x, aH0[p]);
                    aH1[p] = fma2(xv[kx + p], wh.y, aH1[p]);
                }
            }
        }
    }

    int gy = y0 + r;
    ulonglong2* zout = (ulonglong2*)g_zx;
#pragma unroll
    for (int p = 0; p < 8; p++) {
        int gx = x0 + p;
        if (gx < WO) {
            size_t base = (((size_t)frame * HO + gy) * WO + gx) * 16;
            zout[base + fc0] = make_ulonglong2(aL0[p], aH0[p]);
            zout[base + fc1] = make_ulonglong2(aL1[p], aH1[p]);
        }
    }
}

// ---------------- persistent ConvLSTM: all 16 steps in one launch ------------
// 392 blocks (7x7x8), 128 thr = 16 fc x 8 rows; 8 px/thread; c in registers.
// sht rows padded to LH_STRIDE float2 -> conflict-free xv LDS.64.
__global__ __launch_bounds__(128, 3) void lstm_persistent() {
    __shared__ __align__(16) float swh[9 * 16 * 16 * 4];   // 36.8 KB
    __shared__ __align__(16) float2 sht[10 * LH_STRIDE];   // 12.9 KB (duplicated)

    int bid = blockIdx.x;
    int b   = bid / 49;
    int ty  = (bid / 7) % 7, tx = bid % 7;
    int y0  = ty * 8, x0 = tx * 8;
    int tid = threadIdx.x;
    int fc  = tid & 15;
    int r   = tid >> 4;
    int gy  = y0 + r;

    float4* swh4 = (float4*)swh;
    for (int i = tid; i < 2304; i += 128) swh4[i] = g_wh[i];
    __syncthreads();

    float creg[8];
#pragma unroll
    for (int p = 0; p < 8; p++) creg[p] = 0.f;

    const ulonglong2* zin = (const ulonglong2*)g_zx;

#pragma unroll 1
    for (int t = 0; t < NT; t++) {
        ull accL[8], accH[8];
#pragma unroll
        for (int p = 0; p < 8; p++) { accL[p] = 0ULL; accH[p] = 0ULL; }

        if (t > 0) {
            const float* hb = g_h[t & 1] + (size_t)b * HO * WO * NF;
            for (int i = tid; i < 1600; i += 128) {
                int ci  = i & 15;
                int cw  = (i >> 4) % 10;
                int row = (i >> 4) / 10;
                int col = cw + x0 - 1;
                int grow = row + y0 - 1;
                float v = (grow >= 0 && grow < HO && col >= 0 && col < WO)
                              ? hb[(grow * WO + col) * NF + ci] : 0.f;
                sht[row * LH_STRIDE + cw * 16 + ci] = make_float2(v, v);
            }
            __syncthreads();

#pragma unroll 1
            for (int ky = 0; ky < 3; ky++) {
                const ull* hrow = (const ull*)&sht[(r + ky) * LH_STRIDE];
#pragma unroll 1
                for (int cin = 0; cin < 16; cin++) {
                    ull xv[10];
#pragma unroll
                    for (int q = 0; q < 10; q++) xv[q] = hrow[q * 16 + cin];
#pragma unroll
                    for (int kx = 0; kx < 3; kx++) {
                        const ulonglong2 w2 =
                            ((const ulonglong2*)swh4)[((ky * 3 + kx) * 16 + cin) * 16 + fc];
#pragma unroll
                        for (int p = 0; p < 8; p++) {
                            accL[p] = fma2(xv[kx + p], w2.x, accL[p]);
                            accH[p] = fma2(xv[kx + p], w2.y, accH[p]);
                        }
                    }
                }
            }
        }

        if (gy < HO) {
            size_t fbase = ((size_t)(b * NT + t) * HO + gy) * WO;
            float* hout = g_h[(t + 1) & 1];
#pragma unroll
            for (int p = 0; p < 8; p++) {
                int gx = x0 + p;
                if (gx >= WO) continue;
                ulonglong2 zx2 = zin[(fbase + gx) * 16 + fc];
                ull zL = add2(zx2.x, accL[p]);
                ull zH = add2(zx2.y, accH[p]);
                float zi, zf, zg, zo;
                unpack2(zL, zi, zf);
                unpack2(zH, zg, zo);

                float ig = __saturatef(0.2f * zi + 0.5f);
                float fg = __saturatef(0.2f * zf + 0.5f);
                float gg = tanhf(zg);
                float og = __saturatef(0.2f * zo + 0.5f);

                float c_new = fg * creg[p] + ig * gg;
                creg[p] = c_new;
                size_t idx = (((size_t)b * HO + gy) * WO + gx) * NF + fc;
                hout[idx] = og * tanhf(c_new);
            }
        }
        grid_barrier();
    }
}

// ---------------- GAP + dense + softmax ----------------
__global__ __launch_bounds__(256) void head_kernel(
        const float* __restrict__ dw,
        const float* __restrict__ db,
        float* __restrict__ out) {
    int b   = blockIdx.x;
    int tid = threadIdx.x;
    const float* hb = g_h[0] + (size_t)b * HO * WO * NF;  // t=15 wrote buffer 0
    int ch = tid & 15, seg = tid >> 4;

    float s = 0.f;
    for (int p = seg; p < HO * WO; p += 16) s += hb[p * NF + ch];

    __shared__ float part[256];
    __shared__ float mean[16];
    part[tid] = s;
    __syncthreads();
    if (tid < 16) {
        float m = 0.f;
        for (int k = 0; k < 16; k++) m += part[k * 16 + tid];
        mean[tid] = m / (float)(HO * WO);
    }
    __syncthreads();
    if (tid == 0) {
        float logits[NCLS];
        for (int j = 0; j < NCLS; j++) {
            float acc = db[j];
            for (int c = 0; c < 16; c++) acc += mean[c] * dw[c * NCLS + j];
            logits[j] = acc;
        }
        float mx = logits[0];
        for (int j = 1; j < NCLS; j++) mx = fmaxf(mx, logits[j]);
        float sum = 0.f;
        for (int j = 0; j < NCLS; j++) { logits[j] = expf(logits[j] - mx); sum += logits[j]; }
        float inv = 1.f / sum;
        for (int j = 0; j < NCLS; j++) out[b * NCLS + j] = logits[j] * inv;
    }
}

// ---------------- launcher ----------------
extern "C" void kernel_launch(void* const* d_in, const int* in_sizes, int n_in,
                              void* d_out, int out_size) {
    const float* x       = (const float*)d_in[0];
    const float* conv_w  = (const float*)d_in[1];
    const float* conv_b  = (const float*)d_in[2];
    const float* lstm_k  = (const float*)d_in[3];
    const float* lstm_rk = (const float*)d_in[4];
    const float* lstm_b  = (const float*)d_in[5];
    const float* dense_w = (const float*)d_in[6];
    const float* dense_b = (const float*)d_in[7];
    float* out = (float*)d_out;

    // host-side attribute set (idempotent, capture-safe, no allocation)
    cudaFuncSetAttribute(zx_kernel,
                         cudaFuncAttributeMaxDynamicSharedMemorySize,
                         ZX_SMEM_BYTES);

    init_kernel<<<1, 1>>>();
    prep_kernel<<<9, 256>>>(lstm_k, lstm_rk, lstm_b);
    conv_pool_kernel<<<dim3(7, 2, NB * NT), 224>>>(x, conv_w, conv_b);
    zx_kernel<<<dim3(7, 2, NB * NT), 224, ZX_SMEM_BYTES>>>();
    lstm_persistent<<<NBLK_LSTM, 128>>>();
    head_kernel<<<NB, 256>>>(dense_w, dense_b, out);
}